// round 3
// baseline (speedup 1.0000x reference)
#include <cuda_runtime.h>
#include <math.h>
#include <float.h>

#define NNODES 50000
#define NEDGES 400000
#define NGRAPH 256
#define FIN    79
#define DIM    400

// ---------------- scratch (static device globals; no runtime alloc) ----------
__device__ float g_bufA[NNODES * DIM];
__device__ float g_bufB[NNODES * DIM];
__device__ float g_bufC[NNODES * DIM];
__device__ float g_mx[NGRAPH * DIM];
__device__ float g_sm[NGRAPH * DIM];
__device__ float g_cnt[NGRAPH];
__device__ float g_s1[DIM], g_fb1[DIM];   // folded BN1 scale / (bias incl. linear b1)
__device__ float g_s2[DIM], g_fb2[DIM];   // folded BN2

// ---------------- small helpers ---------------------------------------------
__global__ void fold_bn_k(const float* __restrict__ g, const float* __restrict__ b,
                          const float* __restrict__ m, const float* __restrict__ v,
                          const float* __restrict__ lin_b,
                          float* __restrict__ scale, float* __restrict__ bias) {
    int i = blockIdx.x * blockDim.x + threadIdx.x;
    if (i < DIM) {
        float s = g[i] * rsqrtf(v[i] + 1e-5f);
        scale[i] = s;
        bias[i]  = (lin_b[i] - m[i]) * s + b[i];
    }
}

// z = (1 + eps[0]) * h   (grid-stride)
__global__ void scale_copy_k(const float* __restrict__ h, float* __restrict__ z,
                             const float* __restrict__ eps, int total) {
    float e = 1.0f + __ldg(eps);
    for (int i = blockIdx.x * blockDim.x + threadIdx.x; i < total;
         i += gridDim.x * blockDim.x)
        z[i] = e * h[i];
}

// z[dst] += h[src] over edges; one block per edge
__global__ void scatter_add_k(const float* __restrict__ h, float* __restrict__ z,
                              const int* __restrict__ src, const int* __restrict__ dst,
                              int d) {
    int e = blockIdx.x;
    int s = src[e], t = dst[e];
    const float* hr = h + (size_t)s * d;
    float*       zr = z + (size_t)t * d;
    for (int i = threadIdx.x; i < d; i += blockDim.x)
        atomicAdd(&zr[i], hr[i]);
}

// ---------------- GEMM: C[M,DIM] = act((A[M,K] @ B[K,DIM]) * colscale + colbias)
// BM=128, BN=80, BK=16, 256 threads, 8x5 micro-tile per thread.
template <int ACT, bool HAS_SCALE>   // ACT: 0 = relu, 1 = tanh
__launch_bounds__(256)
__global__ void gemm_epi_k(const float* __restrict__ A, const float* __restrict__ B,
                           float* __restrict__ C, int M, int K,
                           const float* __restrict__ colscale,
                           const float* __restrict__ colbias) {
    const int BM = 128, BN = 80, BK = 16;
    __shared__ float As[BK][BM + 4];   // pad 132: kills 16-way STS conflict
    __shared__ float Bs[BK][BN];

    int tid = threadIdx.x;
    int ty = tid >> 4, tx = tid & 15;         // 16 x 16
    int m0 = blockIdx.y * BM;
    int n0 = blockIdx.x * BN;

    float acc[8][5];
#pragma unroll
    for (int i = 0; i < 8; i++)
#pragma unroll
        for (int j = 0; j < 5; j++) acc[i][j] = 0.0f;

    for (int k0 = 0; k0 < K; k0 += BK) {
        // load A tile (128x16)
#pragma unroll
        for (int j = 0; j < 8; j++) {
            int idx = tid + 256 * j;
            int r = idx >> 4, kk = idx & 15;
            int gm = m0 + r, gk = k0 + kk;
            As[kk][r] = (gm < M && gk < K) ? A[(size_t)gm * K + gk] : 0.0f;
        }
        // load B tile (16x80)
#pragma unroll
        for (int j = 0; j < 5; j++) {
            int idx = tid + 256 * j;
            int kk = idx / 80, c = idx - kk * 80;
            int gk = k0 + kk;
            Bs[kk][c] = (gk < K) ? B[(size_t)gk * DIM + n0 + c] : 0.0f;
        }
        __syncthreads();
#pragma unroll
        for (int kk = 0; kk < BK; kk++) {
            float a[8], b[5];
#pragma unroll
            for (int i = 0; i < 8; i++) a[i] = As[kk][ty + 16 * i];
#pragma unroll
            for (int j = 0; j < 5; j++) b[j] = Bs[kk][tx + 16 * j];
#pragma unroll
            for (int i = 0; i < 8; i++)
#pragma unroll
                for (int j = 0; j < 5; j++) acc[i][j] += a[i] * b[j];
        }
        __syncthreads();
    }

#pragma unroll
    for (int j = 0; j < 5; j++) {
        int c = n0 + tx + 16 * j;
        float s  = HAS_SCALE ? colscale[c] : 1.0f;
        float bi = colbias[c];
#pragma unroll
        for (int i = 0; i < 8; i++) {
            int m = m0 + ty + 16 * i;
            if (m < M) {
                float v = acc[i][j] * s + bi;
                if (ACT == 0) v = fmaxf(v, 0.0f);
                else          v = tanhf(v);
                C[(size_t)m * DIM + c] = v;
            }
        }
    }
}

// ---------------- pooling ----------------------------------------------------
__global__ void pool_init_k() {
    for (int i = blockIdx.x * blockDim.x + threadIdx.x; i < NGRAPH * DIM;
         i += gridDim.x * blockDim.x) {
        g_mx[i] = -FLT_MAX;
        g_sm[i] = 0.0f;
        if (i < NGRAPH) g_cnt[i] = 0.0f;
    }
}

__device__ __forceinline__ void atomicMaxF(float* addr, float v) {
    if (v >= 0.0f) atomicMax((int*)addr, __float_as_int(v));
    else           atomicMin((unsigned int*)addr, __float_as_uint(v));
}

__global__ void pool_acc_k(const float* __restrict__ h, const int* __restrict__ batch) {
    for (int i = blockIdx.x * blockDim.x + threadIdx.x; i < NNODES * DIM;
         i += gridDim.x * blockDim.x) {
        int n = i / DIM, d = i - n * DIM;
        int g = batch[n];
        float v = h[i];
        atomicAdd(&g_sm[g * DIM + d], v);
        atomicMaxF(&g_mx[g * DIM + d], v);
    }
}

__global__ void count_k(const int* __restrict__ batch) {
    for (int n = blockIdx.x * blockDim.x + threadIdx.x; n < NNODES;
         n += gridDim.x * blockDim.x)
        atomicAdd(&g_cnt[batch[n]], 1.0f);
}

__global__ void final_k(const float* __restrict__ ow, const float* __restrict__ ob,
                        float* __restrict__ out) {
    int g = blockIdx.x;
    __shared__ float red[256];
    float c = fmaxf(g_cnt[g], 1.0f);
    float acc = 0.0f;
    for (int d = threadIdx.x; d < DIM; d += 256) {
        acc += g_mx[g * DIM + d] * ow[d];
        acc += (g_sm[g * DIM + d] / c) * ow[DIM + d];
    }
    red[threadIdx.x] = acc;
    __syncthreads();
    for (int s = 128; s > 0; s >>= 1) {
        if (threadIdx.x < s) red[threadIdx.x] += red[threadIdx.x + s];
        __syncthreads();
    }
    if (threadIdx.x == 0) out[g] = red[0] + ob[0];
}

// ---------------- orchestration ---------------------------------------------
extern "C" void kernel_launch(void* const* d_in, const int* in_sizes, int n_in,
                              void* d_out, int out_size) {
    const float* x     = (const float*)d_in[0];
    const int*   eidx  = (const int*)d_in[1];
    const int*   batch = (const int*)d_in[2];
    // num_graphs may or may not be materialized as a size-1 input
    int o = (in_sizes[3] == 1) ? 4 : 3;

    const float* m1w1  = (const float*)d_in[o + 0];
    const float* m1b1  = (const float*)d_in[o + 1];
    const float* m1g   = (const float*)d_in[o + 2];
    const float* m1bb  = (const float*)d_in[o + 3];
    const float* m1m   = (const float*)d_in[o + 4];
    const float* m1v   = (const float*)d_in[o + 5];
    const float* m1w2  = (const float*)d_in[o + 6];
    const float* m1b2  = (const float*)d_in[o + 7];
    const float* m2w1  = (const float*)d_in[o + 8];
    const float* m2b1  = (const float*)d_in[o + 9];
    const float* m2g   = (const float*)d_in[o + 10];
    const float* m2bb  = (const float*)d_in[o + 11];
    const float* m2m   = (const float*)d_in[o + 12];
    const float* m2v   = (const float*)d_in[o + 13];
    const float* m2w2  = (const float*)d_in[o + 14];
    const float* m2b2  = (const float*)d_in[o + 15];
    const float* o1w   = (const float*)d_in[o + 16];
    const float* o1b   = (const float*)d_in[o + 17];
    const float* o2w   = (const float*)d_in[o + 18];
    const float* o2b   = (const float*)d_in[o + 19];
    const float* o3w   = (const float*)d_in[o + 20];
    const float* o3b   = (const float*)d_in[o + 21];
    const float* ow    = (const float*)d_in[o + 22];
    const float* ob    = (const float*)d_in[o + 23];
    const float* eps1  = (const float*)d_in[o + 24];
    const float* eps2  = (const float*)d_in[o + 25];
    const float* eps3  = (const float*)d_in[o + 26];

    const int* src = eidx;
    const int* dst = eidx + NEDGES;

    float *bufA, *bufB, *bufC, *s1, *fb1, *s2, *fb2;
    cudaGetSymbolAddress((void**)&bufA, g_bufA);
    cudaGetSymbolAddress((void**)&bufB, g_bufB);
    cudaGetSymbolAddress((void**)&bufC, g_bufC);
    cudaGetSymbolAddress((void**)&s1,  g_s1);
    cudaGetSymbolAddress((void**)&fb1, g_fb1);
    cudaGetSymbolAddress((void**)&s2,  g_s2);
    cudaGetSymbolAddress((void**)&fb2, g_fb2);

    dim3 gemm_grid(DIM / 80, (NNODES + 127) / 128);

    // fold BN params (both layers)
    fold_bn_k<<<2, 256>>>(m1g, m1bb, m1m, m1v, m1b1, s1, fb1);
    fold_bn_k<<<2, 256>>>(m2g, m2bb, m2m, m2v, m2b1, s2, fb2);

    // ---- GIN layer 1 (input dim 79) ----
    scale_copy_k<<<2048, 256>>>(x, bufA, eps1, NNODES * FIN);
    scatter_add_k<<<NEDGES, 128>>>(x, bufA, src, dst, FIN);
    gemm_epi_k<0, true ><<<gemm_grid, 256>>>(bufA, m1w1, bufB, NNODES, FIN, s1, fb1);
    gemm_epi_k<0, false><<<gemm_grid, 256>>>(bufB, m1w2, bufC, NNODES, DIM, nullptr, m1b2);
    gemm_epi_k<1, false><<<gemm_grid, 256>>>(bufC, o1w,  bufA, NNODES, DIM, nullptr, o1b);

    // ---- GIN layer 2 ----
    scale_copy_k<<<2048, 256>>>(bufA, bufB, eps2, NNODES * DIM);
    scatter_add_k<<<NEDGES, 128>>>(bufA, bufB, src, dst, DIM);
    gemm_epi_k<0, true ><<<gemm_grid, 256>>>(bufB, m2w1, bufC, NNODES, DIM, s2, fb2);
    gemm_epi_k<0, false><<<gemm_grid, 256>>>(bufC, m2w2, bufB, NNODES, DIM, nullptr, m2b2);
    gemm_epi_k<1, false><<<gemm_grid, 256>>>(bufB, o2w,  bufA, NNODES, DIM, nullptr, o2b);

    // ---- GIN layer 3 (reuses mlp2 weights, eps3) ----
    scale_copy_k<<<2048, 256>>>(bufA, bufB, eps3, NNODES * DIM);
    scatter_add_k<<<NEDGES, 128>>>(bufA, bufB, src, dst, DIM);
    gemm_epi_k<0, true ><<<gemm_grid, 256>>>(bufB, m2w1, bufC, NNODES, DIM, s2, fb2);
    gemm_epi_k<0, false><<<gemm_grid, 256>>>(bufC, m2w2, bufB, NNODES, DIM, nullptr, m2b2);
    gemm_epi_k<1, false><<<gemm_grid, 256>>>(bufB, o3w,  bufA, NNODES, DIM, nullptr, o3b);

    // ---- pooling + head ----
    pool_init_k<<<128, 256>>>();
    count_k<<<(NNODES + 255) / 256, 256>>>(batch);
    pool_acc_k<<<4096, 256>>>(bufA, batch);
    final_k<<<NGRAPH, 256>>>(ow, ob, (float*)d_out);
}

// round 6
// speedup vs baseline: 1.2273x; 1.2273x over previous
#include <cuda_runtime.h>
#include <math.h>
#include <float.h>
#include <stdint.h>

#define NNODES 50000
#define NEDGES 400000
#define NGRAPH 256
#define FIN    79
#define DIM    400

// ---------------- scratch (static device globals; no runtime alloc) ----------
__device__ float g_bufA[NNODES * DIM];
__device__ float g_bufB[NNODES * DIM];
__device__ float g_bufC[NNODES * DIM];
__device__ float g_mx[NGRAPH * DIM];
__device__ float g_sm[NGRAPH * DIM];
__device__ float g_cnt[NGRAPH];
__device__ float g_s1[DIM], g_fb1[DIM];
__device__ float g_s2[DIM], g_fb2[DIM];
// CSR scratch
__device__ int g_deg[NNODES];
__device__ int g_cursor[NNODES];
__device__ int g_rowptr[NNODES + 1];
__device__ int g_colidx[NEDGES];

// ---------------- BN fold ----------------------------------------------------
__global__ void fold_bn_k(const float* __restrict__ g, const float* __restrict__ b,
                          const float* __restrict__ m, const float* __restrict__ v,
                          const float* __restrict__ lin_b,
                          float* __restrict__ scale, float* __restrict__ bias) {
    int i = blockIdx.x * blockDim.x + threadIdx.x;
    if (i < DIM) {
        float s = g[i] * rsqrtf(v[i] + 1e-5f);
        scale[i] = s;
        bias[i]  = (lin_b[i] - m[i]) * s + b[i];
    }
}

// ---------------- CSR build (per launch) -------------------------------------
__global__ void zero_csr_k(int* deg, int* cursor) {
    int i = blockIdx.x * blockDim.x + threadIdx.x;
    if (i < NNODES) { deg[i] = 0; cursor[i] = 0; }
}

__global__ void hist_k(const int* __restrict__ dst, int* __restrict__ deg) {
    int e = blockIdx.x * blockDim.x + threadIdx.x;
    if (e < NEDGES) atomicAdd(&deg[dst[e]], 1);
}

__global__ void scan_k(const int* __restrict__ deg, int* __restrict__ rowptr) {
    __shared__ int sh[1024];
    __shared__ int s_carry;
    int tid = threadIdx.x;
    if (tid == 0) s_carry = 0;
    __syncthreads();
    for (int base = 0; base < NNODES; base += 1024) {
        int v = (base + tid < NNODES) ? deg[base + tid] : 0;
        sh[tid] = v;
        __syncthreads();
        for (int off = 1; off < 1024; off <<= 1) {
            int add = (tid >= off) ? sh[tid - off] : 0;
            __syncthreads();
            sh[tid] += add;
            __syncthreads();
        }
        if (base + tid < NNODES) rowptr[base + tid] = s_carry + sh[tid] - v;
        __syncthreads();
        if (tid == 1023) s_carry += sh[1023];
        __syncthreads();
    }
    if (tid == 0) rowptr[NNODES] = s_carry;
}

__global__ void fill_k(const int* __restrict__ src, const int* __restrict__ dst,
                       const int* __restrict__ rowptr, int* __restrict__ cursor,
                       int* __restrict__ colidx) {
    int e = blockIdx.x * blockDim.x + threadIdx.x;
    if (e < NEDGES) {
        int d = dst[e];
        int pos = atomicAdd(&cursor[d], 1);
        colidx[rowptr[d] + pos] = src[e];
    }
}

// z[n] = (1+eps)*h[n] + sum_{s in in(n)} h[s]   (gather; h fits in L2)
__global__ void gather_agg_k(const float* __restrict__ h, float* __restrict__ z,
                             const int* __restrict__ rowptr, const int* __restrict__ colidx,
                             const float* __restrict__ eps, int d) {
    int n = blockIdx.x;
    int tid = threadIdx.x;     // 128
    int e0 = rowptr[n], e1 = rowptr[n + 1];
    float coef = 1.0f + __ldg(eps);
    const float* hr = h + (size_t)n * d;
    float acc[4];
#pragma unroll
    for (int j = 0; j < 4; j++) {
        int i = tid + 128 * j;
        acc[j] = (i < d) ? coef * hr[i] : 0.0f;
    }
    for (int e = e0; e < e1; e++) {
        const float* hs = h + (size_t)colidx[e] * d;
#pragma unroll
        for (int j = 0; j < 4; j++) {
            int i = tid + 128 * j;
            if (i < d) acc[j] += hs[i];
        }
    }
    float* zr = z + (size_t)n * d;
#pragma unroll
    for (int j = 0; j < 4; j++) {
        int i = tid + 128 * j;
        if (i < d) zr[i] = acc[j];
    }
}

// ---------------- 3xTF32 tensor-core GEMM -----------------------------------
// C[M,400] = act((A[M,K] @ W[K,400]) * colscale + colbias)
// BM=128 BN=80 BK=16, 256 thr, warps 4(m) x 2(n), warp tile 32x40.
// smem: As[128][20] float2 (20480 B) + Bs[16][84] float2 (10752 B) = 31232 B.
__device__ __forceinline__ float2 tf32_split(float v) {
    float hi = __uint_as_float(__float_as_uint(v) & 0xFFFFE000u);
    float lo = __uint_as_float(__float_as_uint(v - hi) & 0xFFFFE000u);
    return make_float2(hi, lo);
}

__device__ __forceinline__ void mma8(float* c, const uint32_t* a, const uint32_t* b) {
    asm volatile(
        "mma.sync.aligned.m16n8k8.row.col.f32.tf32.tf32.f32 "
        "{%0,%1,%2,%3}, {%4,%5,%6,%7}, {%8,%9}, {%0,%1,%2,%3};"
        : "+f"(c[0]), "+f"(c[1]), "+f"(c[2]), "+f"(c[3])
        : "r"(a[0]), "r"(a[1]), "r"(a[2]), "r"(a[3]), "r"(b[0]), "r"(b[1]));
}

template <int ACT, bool HAS_SCALE>   // ACT: 0 = relu, 1 = tanh
__launch_bounds__(256)
__global__ void gemm_tc_k(const float* __restrict__ A, const float* __restrict__ W,
                          float* __restrict__ C, int M, int K,
                          const float* __restrict__ colscale,
                          const float* __restrict__ colbias) {
    const int BM = 128, BN = 80, BK = 16;
    __shared__ float2 As[BM][20];   // (hi,lo); stride 20: (20g+t)%16 = 4g+t, phase-distinct
    __shared__ float2 Bs[BK][84];   // stride 84: (84t+g)%16 = 4t+g, phase-distinct

    int tid  = threadIdx.x;
    int lane = tid & 31, wid = tid >> 5;
    int warpM = wid & 3, warpN = wid >> 2;
    int g = lane >> 2, t = lane & 3;
    int m0 = blockIdx.y * BM;
    int n0 = blockIdx.x * BN;

    float acc[2][5][4];
#pragma unroll
    for (int mt = 0; mt < 2; mt++)
#pragma unroll
        for (int nt = 0; nt < 5; nt++)
#pragma unroll
            for (int i = 0; i < 4; i++) acc[mt][nt][i] = 0.0f;

    for (int k0 = 0; k0 < K; k0 += BK) {
        // ---- A tile: 128x16 fp32 = 512 float4 slots; 2 per thread ----
#pragma unroll
        for (int i = 0; i < 2; i++) {
            int slot = tid + 256 * i;
            int r = slot >> 2, c4 = (slot & 3) << 2;   // 4 float4-slots per row
            int gm = m0 + r, gk = k0 + c4;
            float4 v = make_float4(0.f, 0.f, 0.f, 0.f);
            if (gm < M) {
                if (((K & 3) == 0) && gk + 3 < K) {
                    v = *(const float4*)(A + (size_t)gm * K + gk);
                } else {
                    if (gk + 0 < K) v.x = A[(size_t)gm * K + gk + 0];
                    if (gk + 1 < K) v.y = A[(size_t)gm * K + gk + 1];
                    if (gk + 2 < K) v.z = A[(size_t)gm * K + gk + 2];
                    if (gk + 3 < K) v.w = A[(size_t)gm * K + gk + 3];
                }
            }
            As[r][c4 + 0] = tf32_split(v.x);
            As[r][c4 + 1] = tf32_split(v.y);
            As[r][c4 + 2] = tf32_split(v.z);
            As[r][c4 + 3] = tf32_split(v.w);
        }
        // ---- B tile: 16x80 fp32 = 320 float4 slots ----
#pragma unroll
        for (int i = 0; i < 2; i++) {
            int slot = tid + 256 * i;
            if (slot < 320) {
                int kk = slot / 20, c4 = (slot % 20) << 2;   // 20 float4-slots per row
                int gk = k0 + kk;
                float4 v = make_float4(0.f, 0.f, 0.f, 0.f);
                if (gk < K) v = *(const float4*)(W + (size_t)gk * DIM + n0 + c4);
                Bs[kk][c4 + 0] = tf32_split(v.x);
                Bs[kk][c4 + 1] = tf32_split(v.y);
                Bs[kk][c4 + 2] = tf32_split(v.z);
                Bs[kk][c4 + 3] = tf32_split(v.w);
            }
        }
        __syncthreads();

#pragma unroll
        for (int kk = 0; kk < 2; kk++) {
            int k8 = kk * 8;
            float2 af[2][4];
#pragma unroll
            for (int mt = 0; mt < 2; mt++) {
                int mb = warpM * 32 + mt * 16;
                af[mt][0] = As[mb + g][k8 + t];
                af[mt][1] = As[mb + g + 8][k8 + t];
                af[mt][2] = As[mb + g][k8 + t + 4];
                af[mt][3] = As[mb + g + 8][k8 + t + 4];
            }
            float2 bf[5][2];
#pragma unroll
            for (int nt = 0; nt < 5; nt++) {
                int nb = warpN * 40 + nt * 8 + g;
                bf[nt][0] = Bs[k8 + t][nb];
                bf[nt][1] = Bs[k8 + t + 4][nb];
            }
#pragma unroll
            for (int mt = 0; mt < 2; mt++) {
                uint32_t ahi[4], alo[4];
#pragma unroll
                for (int i = 0; i < 4; i++) {
                    ahi[i] = __float_as_uint(af[mt][i].x);
                    alo[i] = __float_as_uint(af[mt][i].y);
                }
#pragma unroll
                for (int nt = 0; nt < 5; nt++) {
                    uint32_t bhi[2], blo[2];
                    bhi[0] = __float_as_uint(bf[nt][0].x);
                    bhi[1] = __float_as_uint(bf[nt][1].x);
                    blo[0] = __float_as_uint(bf[nt][0].y);
                    blo[1] = __float_as_uint(bf[nt][1].y);
                    mma8(acc[mt][nt], alo, bhi);   // small terms first
                    mma8(acc[mt][nt], ahi, blo);
                    mma8(acc[mt][nt], ahi, bhi);
                }
            }
        }
        __syncthreads();
    }

    // ---- epilogue: scale/bias + act, float2 stores ----
#pragma unroll
    for (int mt = 0; mt < 2; mt++) {
        int mb = m0 + warpM * 32 + mt * 16;
#pragma unroll
        for (int nt = 0; nt < 5; nt++) {
            int nb = n0 + warpN * 40 + nt * 8 + 2 * t;
            float s0 = HAS_SCALE ? __ldg(&colscale[nb])     : 1.0f;
            float s1 = HAS_SCALE ? __ldg(&colscale[nb + 1]) : 1.0f;
            float b0 = __ldg(&colbias[nb]);
            float b1 = __ldg(&colbias[nb + 1]);
            float* a = acc[mt][nt];
            int r0 = mb + g, r1 = mb + g + 8;
            if (r0 < M) {
                float v0 = a[0] * s0 + b0, v1 = a[1] * s1 + b1;
                if (ACT == 0) { v0 = fmaxf(v0, 0.f); v1 = fmaxf(v1, 0.f); }
                else          { v0 = tanhf(v0);      v1 = tanhf(v1); }
                *(float2*)(C + (size_t)r0 * DIM + nb) = make_float2(v0, v1);
            }
            if (r1 < M) {
                float v0 = a[2] * s0 + b0, v1 = a[3] * s1 + b1;
                if (ACT == 0) { v0 = fmaxf(v0, 0.f); v1 = fmaxf(v1, 0.f); }
                else          { v0 = tanhf(v0);      v1 = tanhf(v1); }
                *(float2*)(C + (size_t)r1 * DIM + nb) = make_float2(v0, v1);
            }
        }
    }
}

// ---------------- pooling ----------------------------------------------------
__global__ void pool_init_k() {
    for (int i = blockIdx.x * blockDim.x + threadIdx.x; i < NGRAPH * DIM;
         i += gridDim.x * blockDim.x) {
        g_mx[i] = -FLT_MAX;
        g_sm[i] = 0.0f;
        if (i < NGRAPH) g_cnt[i] = 0.0f;
    }
}

__device__ __forceinline__ void atomicMaxF(float* addr, float v) {
    if (v >= 0.0f) atomicMax((int*)addr, __float_as_int(v));
    else           atomicMin((unsigned int*)addr, __float_as_uint(v));
}

__global__ void pool_acc_k(const float* __restrict__ h, const int* __restrict__ batch) {
    for (int i = blockIdx.x * blockDim.x + threadIdx.x; i < NNODES * DIM;
         i += gridDim.x * blockDim.x) {
        int n = i / DIM, d = i - n * DIM;
        int g = batch[n];
        float v = h[i];
        atomicAdd(&g_sm[g * DIM + d], v);
        atomicMaxF(&g_mx[g * DIM + d], v);
    }
}

__global__ void count_k(const int* __restrict__ batch) {
    for (int n = blockIdx.x * blockDim.x + threadIdx.x; n < NNODES;
         n += gridDim.x * blockDim.x)
        atomicAdd(&g_cnt[batch[n]], 1.0f);
}

__global__ void final_k(const float* __restrict__ ow, const float* __restrict__ ob,
                        float* __restrict__ out) {
    int g = blockIdx.x;
    __shared__ float red[256];
    float c = fmaxf(g_cnt[g], 1.0f);
    float acc = 0.0f;
    for (int d = threadIdx.x; d < DIM; d += 256) {
        acc += g_mx[g * DIM + d] * ow[d];
        acc += (g_sm[g * DIM + d] / c) * ow[DIM + d];
    }
    red[threadIdx.x] = acc;
    __syncthreads();
    for (int s = 128; s > 0; s >>= 1) {
        if (threadIdx.x < s) red[threadIdx.x] += red[threadIdx.x + s];
        __syncthreads();
    }
    if (threadIdx.x == 0) out[g] = red[0] + ob[0];
}

// ---------------- orchestration ----------------------------------------------
extern "C" void kernel_launch(void* const* d_in, const int* in_sizes, int n_in,
                              void* d_out, int out_size) {
    const float* x     = (const float*)d_in[0];
    const int*   eidx  = (const int*)d_in[1];
    const int*   batch = (const int*)d_in[2];
    int o = (in_sizes[3] == 1) ? 4 : 3;

    const float* m1w1  = (const float*)d_in[o + 0];
    const float* m1b1  = (const float*)d_in[o + 1];
    const float* m1g   = (const float*)d_in[o + 2];
    const float* m1bb  = (const float*)d_in[o + 3];
    const float* m1m   = (const float*)d_in[o + 4];
    const float* m1v   = (const float*)d_in[o + 5];
    const float* m1w2  = (const float*)d_in[o + 6];
    const float* m1b2  = (const float*)d_in[o + 7];
    const float* m2w1  = (const float*)d_in[o + 8];
    const float* m2b1  = (const float*)d_in[o + 9];
    const float* m2g   = (const float*)d_in[o + 10];
    const float* m2bb  = (const float*)d_in[o + 11];
    const float* m2m   = (const float*)d_in[o + 12];
    const float* m2v   = (const float*)d_in[o + 13];
    const float* m2w2  = (const float*)d_in[o + 14];
    const float* m2b2  = (const float*)d_in[o + 15];
    const float* o1w   = (const float*)d_in[o + 16];
    const float* o1b   = (const float*)d_in[o + 17];
    const float* o2w   = (const float*)d_in[o + 18];
    const float* o2b   = (const float*)d_in[o + 19];
    const float* o3w   = (const float*)d_in[o + 20];
    const float* o3b   = (const float*)d_in[o + 21];
    const float* ow    = (const float*)d_in[o + 22];
    const float* ob    = (const float*)d_in[o + 23];
    const float* eps1  = (const float*)d_in[o + 24];
    const float* eps2  = (const float*)d_in[o + 25];
    const float* eps3  = (const float*)d_in[o + 26];

    const int* src = eidx;
    const int* dst = eidx + NEDGES;

    float *bufA, *bufB, *bufC, *s1, *fb1, *s2, *fb2;
    int *deg, *cursor, *rowptr, *colidx;
    cudaGetSymbolAddress((void**)&bufA, g_bufA);
    cudaGetSymbolAddress((void**)&bufB, g_bufB);
    cudaGetSymbolAddress((void**)&bufC, g_bufC);
    cudaGetSymbolAddress((void**)&s1,  g_s1);
    cudaGetSymbolAddress((void**)&fb1, g_fb1);
    cudaGetSymbolAddress((void**)&s2,  g_s2);
    cudaGetSymbolAddress((void**)&fb2, g_fb2);
    cudaGetSymbolAddress((void**)&deg,    g_deg);
    cudaGetSymbolAddress((void**)&cursor, g_cursor);
    cudaGetSymbolAddress((void**)&rowptr, g_rowptr);
    cudaGetSymbolAddress((void**)&colidx, g_colidx);

    dim3 gemm_grid(DIM / 80, (NNODES + 127) / 128);

    // BN fold + CSR build (same graph reused by all 3 layers)
    fold_bn_k<<<2, 256>>>(m1g, m1bb, m1m, m1v, m1b1, s1, fb1);
    fold_bn_k<<<2, 256>>>(m2g, m2bb, m2m, m2v, m2b1, s2, fb2);
    zero_csr_k<<<(NNODES + 255) / 256, 256>>>(deg, cursor);
    hist_k<<<(NEDGES + 255) / 256, 256>>>(dst, deg);
    scan_k<<<1, 1024>>>(deg, rowptr);
    fill_k<<<(NEDGES + 255) / 256, 256>>>(src, dst, rowptr, cursor, colidx);

    // ---- GIN layer 1 (input dim 79) ----
    gather_agg_k<<<NNODES, 128>>>(x, bufA, rowptr, colidx, eps1, FIN);
    gemm_tc_k<0, true ><<<gemm_grid, 256>>>(bufA, m1w1, bufB, NNODES, FIN, s1, fb1);
    gemm_tc_k<0, false><<<gemm_grid, 256>>>(bufB, m1w2, bufC, NNODES, DIM, nullptr, m1b2);
    gemm_tc_k<1, false><<<gemm_grid, 256>>>(bufC, o1w,  bufA, NNODES, DIM, nullptr, o1b);

    // ---- GIN layer 2 ----
    gather_agg_k<<<NNODES, 128>>>(bufA, bufB, rowptr, colidx, eps2, DIM);
    gemm_tc_k<0, true ><<<gemm_grid, 256>>>(bufB, m2w1, bufC, NNODES, DIM, s2, fb2);
    gemm_tc_k<0, false><<<gemm_grid, 256>>>(bufC, m2w2, bufB, NNODES, DIM, nullptr, m2b2);
    gemm_tc_k<1, false><<<gemm_grid, 256>>>(bufB, o2w,  bufA, NNODES, DIM, nullptr, o2b);

    // ---- GIN layer 3 (reuses mlp2 weights, eps3) ----
    gather_agg_k<<<NNODES, 128>>>(bufA, bufB, rowptr, colidx, eps3, DIM);
    gemm_tc_k<0, true ><<<gemm_grid, 256>>>(bufB, m2w1, bufC, NNODES, DIM, s2, fb2);
    gemm_tc_k<0, false><<<gemm_grid, 256>>>(bufC, m2w2, bufB, NNODES, DIM, nullptr, m2b2);
    gemm_tc_k<1, false><<<gemm_grid, 256>>>(bufB, o3w,  bufA, NNODES, DIM, nullptr, o3b);

    // ---- pooling + head ----
    pool_init_k<<<128, 256>>>();
    count_k<<<(NNODES + 255) / 256, 256>>>(batch);
    pool_acc_k<<<4096, 256>>>(bufA, batch);
    final_k<<<NGRAPH, 256>>>(ow, ob, (float*)d_out);
}

// round 12
// speedup vs baseline: 1.7738x; 1.4452x over previous
#include <cuda_runtime.h>
#include <cuda_bf16.h>
#include <math.h>
#include <float.h>
#include <stdint.h>

#define NNODES 50000
#define NEDGES 400000
#define NGRAPH 256
#define FIN    79
#define DIM    400

// packed-pair weight planes: [Kpad/2][400] uint32 (two adjacent-k bf16 per word)
#define KPAD1  96               // K=79  -> 48 pair-rows
#define KPADB  416              // K=400 -> 208 pair-rows
#define WROWS1 (KPAD1/2)
#define WROWSB (KPADB/2)
#define OFF_W1    0
#define OFF_M1W2  (WROWS1*400)
#define OFF_M2W1  (OFF_M1W2 + WROWSB*400)
#define OFF_M2W2  (OFF_M2W1 + WROWSB*400)
#define OFF_O1W   (OFF_M2W2 + WROWSB*400)
#define OFF_O2W   (OFF_O1W  + WROWSB*400)
#define OFF_O3W   (OFF_O2W  + WROWSB*400)
#define WTOTAL    (OFF_O3W  + WROWSB*400)

// ---------------- scratch (static device globals; no runtime alloc) ----------
__device__ float g_bufA[NNODES * DIM];
__device__ float g_bufB[NNODES * DIM];
__device__ float g_bufC[NNODES * DIM];
__device__ float g_mx[NGRAPH * DIM];
__device__ float g_sm[NGRAPH * DIM];
__device__ float g_cnt[NGRAPH];
__device__ float g_s1[DIM], g_fb1[DIM];
__device__ float g_s2[DIM], g_fb2[DIM];
__device__ uint32_t g_wph[WTOTAL];   // hi plane (packed bf16 pairs)
__device__ uint32_t g_wpl[WTOTAL];   // lo plane
// CSR scratch
__device__ int g_deg[NNODES];
__device__ int g_cursor[NNODES];
__device__ int g_rowptr[NNODES + 1];
__device__ int g_colidx[NEDGES];

// ---------------- BN fold ----------------------------------------------------
__global__ void fold_bn_k(const float* __restrict__ g, const float* __restrict__ b,
                          const float* __restrict__ m, const float* __restrict__ v,
                          const float* __restrict__ lin_b,
                          float* __restrict__ scale, float* __restrict__ bias) {
    int i = blockIdx.x * blockDim.x + threadIdx.x;
    if (i < DIM) {
        float s = g[i] * rsqrtf(v[i] + 1e-5f);
        scale[i] = s;
        bias[i]  = (lin_b[i] - m[i]) * s + b[i];
    }
}

// ---------------- weight split: W[K,400] fp32 -> packed-pair bf16 planes -----
__device__ __forceinline__ uint32_t pack_bf16(float a, float b) {
    __nv_bfloat16 x = __float2bfloat16_rn(a), y = __float2bfloat16_rn(b);
    return ((uint32_t)__bfloat16_as_ushort(y) << 16) | __bfloat16_as_ushort(x);
}

__global__ void wsplit_k(const float* __restrict__ W, uint32_t* __restrict__ hi,
                         uint32_t* __restrict__ lo, int K, int rows) {
    int i = blockIdx.x * blockDim.x + threadIdx.x;
    int total = rows * 400;
    if (i < total) {
        int kp = i / 400, n = i - kp * 400;
        int k0 = 2 * kp, k1 = 2 * kp + 1;
        float v0 = (k0 < K) ? W[(size_t)k0 * 400 + n] : 0.0f;
        float v1 = (k1 < K) ? W[(size_t)k1 * 400 + n] : 0.0f;
        float h0 = __bfloat162float(__float2bfloat16_rn(v0));
        float h1 = __bfloat162float(__float2bfloat16_rn(v1));
        hi[i] = pack_bf16(v0, v1);
        lo[i] = pack_bf16(v0 - h0, v1 - h1);
    }
}

// ---------------- CSR build --------------------------------------------------
__global__ void zero_csr_k(int* deg, int* cursor) {
    int i = blockIdx.x * blockDim.x + threadIdx.x;
    if (i < NNODES) { deg[i] = 0; cursor[i] = 0; }
}
__global__ void hist_k(const int* __restrict__ dst, int* __restrict__ deg) {
    int e = blockIdx.x * blockDim.x + threadIdx.x;
    if (e < NEDGES) atomicAdd(&deg[dst[e]], 1);
}
__global__ void scan_k(const int* __restrict__ deg, int* __restrict__ rowptr) {
    __shared__ int sh[1024];
    __shared__ int s_carry;
    int tid = threadIdx.x;
    if (tid == 0) s_carry = 0;
    __syncthreads();
    for (int base = 0; base < NNODES; base += 1024) {
        int v = (base + tid < NNODES) ? deg[base + tid] : 0;
        sh[tid] = v;
        __syncthreads();
        for (int off = 1; off < 1024; off <<= 1) {
            int add = (tid >= off) ? sh[tid - off] : 0;
            __syncthreads();
            sh[tid] += add;
            __syncthreads();
        }
        if (base + tid < NNODES) rowptr[base + tid] = s_carry + sh[tid] - v;
        __syncthreads();
        if (tid == 1023) s_carry += sh[1023];
        __syncthreads();
    }
    if (tid == 0) rowptr[NNODES] = s_carry;
}
__global__ void fill_k(const int* __restrict__ src, const int* __restrict__ dst,
                       const int* __restrict__ rowptr, int* __restrict__ cursor,
                       int* __restrict__ colidx) {
    int e = blockIdx.x * blockDim.x + threadIdx.x;
    if (e < NEDGES) {
        int d = dst[e];
        int pos = atomicAdd(&cursor[d], 1);
        colidx[rowptr[d] + pos] = src[e];
    }
}

// z[n] = (1+eps)*h[n] + sum_{s in in(n)} h[s]
__global__ void gather_agg_k(const float* __restrict__ h, float* __restrict__ z,
                             const int* __restrict__ rowptr, const int* __restrict__ colidx,
                             const float* __restrict__ eps, int d) {
    int n = blockIdx.x;
    int tid = threadIdx.x;     // 128
    int e0 = rowptr[n], e1 = rowptr[n + 1];
    float coef = 1.0f + __ldg(eps);
    const float* hr = h + (size_t)n * d;
    float acc[4];
#pragma unroll
    for (int j = 0; j < 4; j++) {
        int i = tid + 128 * j;
        acc[j] = (i < d) ? coef * hr[i] : 0.0f;
    }
    for (int e = e0; e < e1; e++) {
        const float* hs = h + (size_t)colidx[e] * d;
#pragma unroll
        for (int j = 0; j < 4; j++) {
            int i = tid + 128 * j;
            if (i < d) acc[j] += hs[i];
        }
    }
    float* zr = z + (size_t)n * d;
#pragma unroll
    for (int j = 0; j < 4; j++) {
        int i = tid + 128 * j;
        if (i < d) zr[i] = acc[j];
    }
}

// ---------------- 3x-bf16 tensor-core GEMM (mma.sync m16n8k16) ---------------
// C[M,400] = act((A[M,K] @ W[K,400]) * colscale + colbias)
// BM=128 BN=80 BK=32, 256 thr, warps 4(m) x 2(n), warp tile 32x40.
// smem: Ahi/Alo [128][20] u32 (20480 B) + Bhi/Blo [16][88] u32 (11264 B).
#define A_STR 20
#define B_STR 88

__device__ __forceinline__ void mma16(float* c, const uint32_t* a, const uint32_t* b) {
    asm volatile(
        "mma.sync.aligned.m16n8k16.row.col.f32.bf16.bf16.f32 "
        "{%0,%1,%2,%3}, {%4,%5,%6,%7}, {%8,%9}, {%0,%1,%2,%3};"
        : "+f"(c[0]), "+f"(c[1]), "+f"(c[2]), "+f"(c[3])
        : "r"(a[0]), "r"(a[1]), "r"(a[2]), "r"(a[3]), "r"(b[0]), "r"(b[1]));
}

template <int ACT, bool HAS_SCALE>   // ACT: 0 = relu, 1 = tanh
__launch_bounds__(256)
__global__ void gemm_bf_k(const float* __restrict__ A,
                          const uint32_t* __restrict__ Whi,
                          const uint32_t* __restrict__ Wlo,
                          float* __restrict__ C, int M, int K, int Kpad,
                          const float* __restrict__ colscale,
                          const float* __restrict__ colbias) {
    __shared__ uint32_t Ahi[128 * A_STR], Alo[128 * A_STR];
    __shared__ uint32_t Bhi[16 * B_STR],  Blo[16 * B_STR];

    int tid  = threadIdx.x;
    int lane = tid & 31, wid = tid >> 5;
    int warpM = wid & 3, warpN = wid >> 2;
    int g = lane >> 2, t = lane & 3;
    int m0 = blockIdx.y * 128;
    int n0 = blockIdx.x * 80;

    float acc[2][5][4];
#pragma unroll
    for (int mt = 0; mt < 2; mt++)
#pragma unroll
        for (int nt = 0; nt < 5; nt++)
#pragma unroll
            for (int i = 0; i < 4; i++) acc[mt][nt][i] = 0.0f;

    bool vec4 = ((K & 3) == 0);
    int ntk = Kpad >> 5;

    for (int tk = 0; tk < ntk; tk++) {
        int k0 = tk << 5;
        // ---- A tile: 128 rows x 32 cols fp32 = 1024 float4 slots ----
#pragma unroll
        for (int i = 0; i < 4; i++) {
            int slot = tid + (i << 8);
            int r = slot >> 3, c4 = (slot & 7) << 2;   // 8 float4-slots per row
            int gm = m0 + r, gk = k0 + c4;
            float4 v = make_float4(0.f, 0.f, 0.f, 0.f);
            if (gm < M) {
                if (vec4 && gk + 3 < K) {
                    v = *(const float4*)(A + (size_t)gm * K + gk);
                } else {
                    if (gk + 0 < K) v.x = A[(size_t)gm * K + gk + 0];
                    if (gk + 1 < K) v.y = A[(size_t)gm * K + gk + 1];
                    if (gk + 2 < K) v.z = A[(size_t)gm * K + gk + 2];
                    if (gk + 3 < K) v.w = A[(size_t)gm * K + gk + 3];
                }
            }
            float hx = __bfloat162float(__float2bfloat16_rn(v.x));
            float hy = __bfloat162float(__float2bfloat16_rn(v.y));
            float hz = __bfloat162float(__float2bfloat16_rn(v.z));
            float hw = __bfloat162float(__float2bfloat16_rn(v.w));
            int widx = r * A_STR + (c4 >> 1);
            *(uint2*)&Ahi[widx] = make_uint2(pack_bf16(v.x, v.y), pack_bf16(v.z, v.w));
            *(uint2*)&Alo[widx] = make_uint2(pack_bf16(v.x - hx, v.y - hy),
                                             pack_bf16(v.z - hz, v.w - hw));
        }
        // ---- B tiles: 16 pair-rows x 80 words; straight uint4 copy ----
        {
            int kp0 = tk << 4;
#pragma unroll
            for (int i = 0; i < 2; i++) {
                int slot = tid + (i << 8);
                if (slot < 320) {
                    int r = slot / 20, q = slot % 20;
                    size_t gg = (size_t)(kp0 + r) * 400 + n0 + (q << 2);
                    int widx = r * B_STR + (q << 2);
                    *(uint4*)&Bhi[widx] = *(const uint4*)(Whi + gg);
                    *(uint4*)&Blo[widx] = *(const uint4*)(Wlo + gg);
                }
            }
        }
        __syncthreads();

#pragma unroll
        for (int s = 0; s < 2; s++) {
            int kp = (s << 3) + t;
            uint32_t ah[2][4], al[2][4];
#pragma unroll
            for (int mt = 0; mt < 2; mt++) {
                int base = (warpM * 32 + mt * 16 + g) * A_STR + kp;
                ah[mt][0] = Ahi[base];
                ah[mt][1] = Ahi[base + 8 * A_STR];
                ah[mt][2] = Ahi[base + 4];
                ah[mt][3] = Ahi[base + 8 * A_STR + 4];
                al[mt][0] = Alo[base];
                al[mt][1] = Alo[base + 8 * A_STR];
                al[mt][2] = Alo[base + 4];
                al[mt][3] = Alo[base + 8 * A_STR + 4];
            }
            uint32_t bh[5][2], bl[5][2];
#pragma unroll
            for (int nt = 0; nt < 5; nt++) {
                int idx = kp * B_STR + warpN * 40 + nt * 8 + g;
                bh[nt][0] = Bhi[idx];
                bh[nt][1] = Bhi[idx + 4 * B_STR];
                bl[nt][0] = Blo[idx];
                bl[nt][1] = Blo[idx + 4 * B_STR];
            }
#pragma unroll
            for (int mt = 0; mt < 2; mt++)
#pragma unroll
                for (int nt = 0; nt < 5; nt++) {
                    mma16(acc[mt][nt], al[mt], bh[nt]);   // small terms first
                    mma16(acc[mt][nt], ah[mt], bl[nt]);
                    mma16(acc[mt][nt], ah[mt], bh[nt]);
                }
        }
        __syncthreads();
    }

    // ---- epilogue: scale/bias + act, float2 stores ----
#pragma unroll
    for (int mt = 0; mt < 2; mt++) {
        int mb = m0 + warpM * 32 + mt * 16;
#pragma unroll
        for (int nt = 0; nt < 5; nt++) {
            int nb = n0 + warpN * 40 + nt * 8 + 2 * t;
            float s0 = HAS_SCALE ? __ldg(&colscale[nb])     : 1.0f;
            float s1 = HAS_SCALE ? __ldg(&colscale[nb + 1]) : 1.0f;
            float b0 = __ldg(&colbias[nb]);
            float b1 = __ldg(&colbias[nb + 1]);
            float* a = acc[mt][nt];
            int r0 = mb + g, r1 = mb + g + 8;
            if (r0 < M) {
                float v0 = a[0] * s0 + b0, v1 = a[1] * s1 + b1;
                if (ACT == 0) { v0 = fmaxf(v0, 0.f); v1 = fmaxf(v1, 0.f); }
                else          { v0 = tanhf(v0);      v1 = tanhf(v1); }
                *(float2*)(C + (size_t)r0 * DIM + nb) = make_float2(v0, v1);
            }
            if (r1 < M) {
                float v0 = a[2] * s0 + b0, v1 = a[3] * s1 + b1;
                if (ACT == 0) { v0 = fmaxf(v0, 0.f); v1 = fmaxf(v1, 0.f); }
                else          { v0 = tanhf(v0);      v1 = tanhf(v1); }
                *(float2*)(C + (size_t)r1 * DIM + nb) = make_float2(v0, v1);
            }
        }
    }
}

// ---------------- pooling ----------------------------------------------------
__global__ void pool_init_k() {
    for (int i = blockIdx.x * blockDim.x + threadIdx.x; i < NGRAPH * DIM;
         i += gridDim.x * blockDim.x) {
        g_mx[i] = -FLT_MAX;
        g_sm[i] = 0.0f;
        if (i < NGRAPH) g_cnt[i] = 0.0f;
    }
}
__device__ __forceinline__ void atomicMaxF(float* addr, float v) {
    if (v >= 0.0f) atomicMax((int*)addr, __float_as_int(v));
    else           atomicMin((unsigned int*)addr, __float_as_uint(v));
}
__global__ void pool_acc_k(const float* __restrict__ h, const int* __restrict__ batch) {
    for (int i = blockIdx.x * blockDim.x + threadIdx.x; i < NNODES * DIM;
         i += gridDim.x * blockDim.x) {
        int n = i / DIM, d = i - n * DIM;
        int g = batch[n];
        float v = h[i];
        atomicAdd(&g_sm[g * DIM + d], v);
        atomicMaxF(&g_mx[g * DIM + d], v);
    }
}
__global__ void count_k(const int* __restrict__ batch) {
    for (int n = blockIdx.x * blockDim.x + threadIdx.x; n < NNODES;
         n += gridDim.x * blockDim.x)
        atomicAdd(&g_cnt[batch[n]], 1.0f);
}
__global__ void final_k(const float* __restrict__ ow, const float* __restrict__ ob,
                        float* __restrict__ out) {
    int g = blockIdx.x;
    __shared__ float red[256];
    float c = fmaxf(g_cnt[g], 1.0f);
    float acc = 0.0f;
    for (int d = threadIdx.x; d < DIM; d += 256) {
        acc += g_mx[g * DIM + d] * ow[d];
        acc += (g_sm[g * DIM + d] / c) * ow[DIM + d];
    }
    red[threadIdx.x] = acc;
    __syncthreads();
    for (int s = 128; s > 0; s >>= 1) {
        if (threadIdx.x < s) red[threadIdx.x] += red[threadIdx.x + s];
        __syncthreads();
    }
    if (threadIdx.x == 0) out[g] = red[0] + ob[0];
}

// ---------------- orchestration ----------------------------------------------
extern "C" void kernel_launch(void* const* d_in, const int* in_sizes, int n_in,
                              void* d_out, int out_size) {
    const float* x     = (const float*)d_in[0];
    const int*   eidx  = (const int*)d_in[1];
    const int*   batch = (const int*)d_in[2];
    int o = (in_sizes[3] == 1) ? 4 : 3;

    const float* m1w1  = (const float*)d_in[o + 0];
    const float* m1b1  = (const float*)d_in[o + 1];
    const float* m1g   = (const float*)d_in[o + 2];
    const float* m1bb  = (const float*)d_in[o + 3];
    const float* m1m   = (const float*)d_in[o + 4];
    const float* m1v   = (const float*)d_in[o + 5];
    const float* m1w2  = (const float*)d_in[o + 6];
    const float* m1b2  = (const float*)d_in[o + 7];
    const float* m2w1  = (const float*)d_in[o + 8];
    const float* m2b1  = (const float*)d_in[o + 9];
    const float* m2g   = (const float*)d_in[o + 10];
    const float* m2bb  = (const float*)d_in[o + 11];
    const float* m2m   = (const float*)d_in[o + 12];
    const float* m2v   = (const float*)d_in[o + 13];
    const float* m2w2  = (const float*)d_in[o + 14];
    const float* m2b2  = (const float*)d_in[o + 15];
    const float* o1w   = (const float*)d_in[o + 16];
    const float* o1b   = (const float*)d_in[o + 17];
    const float* o2w   = (const float*)d_in[o + 18];
    const float* o2b   = (const float*)d_in[o + 19];
    const float* o3w   = (const float*)d_in[o + 20];
    const float* o3b   = (const float*)d_in[o + 21];
    const float* ow    = (const float*)d_in[o + 22];
    const float* ob    = (const float*)d_in[o + 23];
    const float* eps1  = (const float*)d_in[o + 24];
    const float* eps2  = (const float*)d_in[o + 25];
    const float* eps3  = (const float*)d_in[o + 26];

    const int* src = eidx;
    const int* dst = eidx + NEDGES;

    float *bufA, *bufB, *bufC, *s1, *fb1, *s2, *fb2;
    int *deg, *cursor, *rowptr, *colidx;
    uint32_t *wph, *wpl;
    cudaGetSymbolAddress((void**)&bufA, g_bufA);
    cudaGetSymbolAddress((void**)&bufB, g_bufB);
    cudaGetSymbolAddress((void**)&bufC, g_bufC);
    cudaGetSymbolAddress((void**)&s1,  g_s1);
    cudaGetSymbolAddress((void**)&fb1, g_fb1);
    cudaGetSymbolAddress((void**)&s2,  g_s2);
    cudaGetSymbolAddress((void**)&fb2, g_fb2);
    cudaGetSymbolAddress((void**)&deg,    g_deg);
    cudaGetSymbolAddress((void**)&cursor, g_cursor);
    cudaGetSymbolAddress((void**)&rowptr, g_rowptr);
    cudaGetSymbolAddress((void**)&colidx, g_colidx);
    cudaGetSymbolAddress((void**)&wph, g_wph);
    cudaGetSymbolAddress((void**)&wpl, g_wpl);

    dim3 ggrid(DIM / 80, (NNODES + 127) / 128);   // (5, 391)

    // BN fold + weight split + CSR build
    fold_bn_k<<<2, 256>>>(m1g, m1bb, m1m, m1v, m1b1, s1, fb1);
    fold_bn_k<<<2, 256>>>(m2g, m2bb, m2m, m2v, m2b1, s2, fb2);
    wsplit_k<<<(WROWS1 * 400 + 255) / 256, 256>>>(m1w1, wph + OFF_W1,   wpl + OFF_W1,   FIN, WROWS1);
    wsplit_k<<<(WROWSB * 400 + 255) / 256, 256>>>(m1w2, wph + OFF_M1W2, wpl + OFF_M1W2, DIM, WROWSB);
    wsplit_k<<<(WROWSB * 400 + 255) / 256, 256>>>(m2w1, wph + OFF_M2W1, wpl + OFF_M2W1, DIM, WROWSB);
    wsplit_k<<<(WROWSB * 400 + 255) / 256, 256>>>(m2w2, wph + OFF_M2W2, wpl + OFF_M2W2, DIM, WROWSB);
    wsplit_k<<<(WROWSB * 400 + 255) / 256, 256>>>(o1w,  wph + OFF_O1W,  wpl + OFF_O1W,  DIM, WROWSB);
    wsplit_k<<<(WROWSB * 400 + 255) / 256, 256>>>(o2w,  wph + OFF_O2W,  wpl + OFF_O2W,  DIM, WROWSB);
    wsplit_k<<<(WROWSB * 400 + 255) / 256, 256>>>(o3w,  wph + OFF_O3W,  wpl + OFF_O3W,  DIM, WROWSB);
    zero_csr_k<<<(NNODES + 255) / 256, 256>>>(deg, cursor);
    hist_k<<<(NEDGES + 255) / 256, 256>>>(dst, deg);
    scan_k<<<1, 1024>>>(deg, rowptr);
    fill_k<<<(NEDGES + 255) / 256, 256>>>(src, dst, rowptr, cursor, colidx);

    // ---- GIN layer 1 (K=79) ----
    gather_agg_k<<<NNODES, 128>>>(x, bufA, rowptr, colidx, eps1, FIN);
    gemm_bf_k<0, true ><<<ggrid, 256>>>(bufA, wph + OFF_W1,   wpl + OFF_W1,   bufB, NNODES, FIN, KPAD1, s1, fb1);
    gemm_bf_k<0, false><<<ggrid, 256>>>(bufB, wph + OFF_M1W2, wpl + OFF_M1W2, bufC, NNODES, DIM, KPADB, nullptr, m1b2);
    gemm_bf_k<1, false><<<ggrid, 256>>>(bufC, wph + OFF_O1W,  wpl + OFF_O1W,  bufA, NNODES, DIM, KPADB, nullptr, o1b);

    // ---- GIN layer 2 ----
    gather_agg_k<<<NNODES, 128>>>(bufA, bufB, rowptr, colidx, eps2, DIM);
    gemm_bf_k<0, true ><<<ggrid, 256>>>(bufB, wph + OFF_M2W1, wpl + OFF_M2W1, bufC, NNODES, DIM, KPADB, s2, fb2);
    gemm_bf_k<0, false><<<ggrid, 256>>>(bufC, wph + OFF_M2W2, wpl + OFF_M2W2, bufB, NNODES, DIM, KPADB, nullptr, m2b2);
    gemm_bf_k<1, false><<<ggrid, 256>>>(bufB, wph + OFF_O2W,  wpl + OFF_O2W,  bufA, NNODES, DIM, KPADB, nullptr, o2b);

    // ---- GIN layer 3 (mlp2 weights, eps3) ----
    gather_agg_k<<<NNODES, 128>>>(bufA, bufB, rowptr, colidx, eps3, DIM);
    gemm_bf_k<0, true ><<<ggrid, 256>>>(bufB, wph + OFF_M2W1, wpl + OFF_M2W1, bufC, NNODES, DIM, KPADB, s2, fb2);
    gemm_bf_k<0, false><<<ggrid, 256>>>(bufC, wph + OFF_M2W2, wpl + OFF_M2W2, bufB, NNODES, DIM, KPADB, nullptr, m2b2);
    gemm_bf_k<1, false><<<ggrid, 256>>>(bufB, wph + OFF_O3W,  wpl + OFF_O3W,  bufA, NNODES, DIM, KPADB, nullptr, o3b);

    // ---- pooling + head ----
    pool_init_k<<<128, 256>>>();
    count_k<<<(NNODES + 255) / 256, 256>>>(batch);
    pool_acc_k<<<4096, 256>>>(bufA, batch);
    final_k<<<NGRAPH, 256>>>(ow, ob, (float*)d_out);
}

// round 17
// speedup vs baseline: 2.4528x; 1.3828x over previous
#include <cuda_runtime.h>
#include <cuda_bf16.h>
#include <math.h>
#include <float.h>
#include <stdint.h>

#define NNODES 50000
#define NEDGES 400000
#define NGRAPH 256
#define FIN    79
#define DIM    400

// packed-pair weight planes: [Kpad/2][400] uint32 (two adjacent-k bf16 per word)
#define KPAD1  96               // K=79  -> 48 pair-rows
#define KPADB  416              // K=400 -> 208 pair-rows
#define WROWS1 (KPAD1/2)
#define WROWSB (KPADB/2)
#define PWORDS 208              // pair-words per activation row (= WROWSB)
#define OFF_W1    0
#define OFF_M1W2  (WROWS1*400)
#define OFF_M2W1  (OFF_M1W2 + WROWSB*400)
#define OFF_M2W2  (OFF_M2W1 + WROWSB*400)
#define OFF_O1W   (OFF_M2W2 + WROWSB*400)
#define OFF_O2W   (OFF_O1W  + WROWSB*400)
#define OFF_O3W   (OFF_O2W  + WROWSB*400)
#define WTOTAL    (OFF_O3W  + WROWSB*400)

// ---------------- scratch (static device globals; no runtime alloc) ----------
__device__ float g_bufA[NNODES * DIM];
__device__ float g_bufB[NNODES * DIM];
__device__ float g_mx[NGRAPH * DIM];
__device__ float g_sm[NGRAPH * DIM];
__device__ float g_cnt[NGRAPH];
__device__ float g_s1[DIM], g_fb1[DIM];
__device__ float g_s2[DIM], g_fb2[DIM];
__device__ uint32_t g_wph[WTOTAL];   // weight hi plane
__device__ uint32_t g_wpl[WTOTAL];   // weight lo plane
// split activation planes (pair-cols 200..207 never written -> stay zero-init)
__device__ uint32_t g_p1h[NNODES * PWORDS];
__device__ uint32_t g_p1l[NNODES * PWORDS];
__device__ uint32_t g_p2h[NNODES * PWORDS];
__device__ uint32_t g_p2l[NNODES * PWORDS];
// CSR scratch
__device__ int g_deg[NNODES];
__device__ int g_cursor[NNODES];
__device__ int g_rowptr[NNODES + 1];
__device__ int g_colidx[NEDGES];

// ---------------- helpers ----------------------------------------------------
__device__ __forceinline__ uint32_t smem_u32(const void* p) {
    uint32_t a;
    asm("{ .reg .u64 t; cvta.to.shared.u64 t, %1; cvt.u32.u64 %0, t; }" : "=r"(a) : "l"(p));
    return a;
}
#define CP16(daddr, sptr) \
    asm volatile("cp.async.ca.shared.global [%0], [%1], 16;" :: "r"(daddr), "l"(sptr))
#define CP_COMMIT() asm volatile("cp.async.commit_group;" ::: "memory")
#define CP_WAIT1()  asm volatile("cp.async.wait_group 1;" ::: "memory")

__device__ __forceinline__ uint32_t pack_bf16(float a, float b) {
    __nv_bfloat16 x = __float2bfloat16_rn(a), y = __float2bfloat16_rn(b);
    return ((uint32_t)__bfloat16_as_ushort(y) << 16) | __bfloat16_as_ushort(x);
}

__device__ __forceinline__ void mma16(float* c, const uint32_t* a, const uint32_t* b) {
    asm volatile(
        "mma.sync.aligned.m16n8k16.row.col.f32.bf16.bf16.f32 "
        "{%0,%1,%2,%3}, {%4,%5,%6,%7}, {%8,%9}, {%0,%1,%2,%3};"
        : "+f"(c[0]), "+f"(c[1]), "+f"(c[2]), "+f"(c[3])
        : "r"(a[0]), "r"(a[1]), "r"(a[2]), "r"(a[3]), "r"(b[0]), "r"(b[1]));
}

// ---------------- BN fold ----------------------------------------------------
__global__ void fold_bn_k(const float* __restrict__ g, const float* __restrict__ b,
                          const float* __restrict__ m, const float* __restrict__ v,
                          const float* __restrict__ lin_b,
                          float* __restrict__ scale, float* __restrict__ bias) {
    int i = blockIdx.x * blockDim.x + threadIdx.x;
    if (i < DIM) {
        float s = g[i] * rsqrtf(v[i] + 1e-5f);
        scale[i] = s;
        bias[i]  = (lin_b[i] - m[i]) * s + b[i];
    }
}

// ---------------- weight split: W[K,400] fp32 -> packed-pair bf16 planes -----
__global__ void wsplit_k(const float* __restrict__ W, uint32_t* __restrict__ hi,
                         uint32_t* __restrict__ lo, int K, int rows) {
    int i = blockIdx.x * blockDim.x + threadIdx.x;
    int total = rows * 400;
    if (i < total) {
        int kp = i / 400, n = i - kp * 400;
        int k0 = 2 * kp, k1 = 2 * kp + 1;
        float v0 = (k0 < K) ? W[(size_t)k0 * 400 + n] : 0.0f;
        float v1 = (k1 < K) ? W[(size_t)k1 * 400 + n] : 0.0f;
        float h0 = __bfloat162float(__float2bfloat16_rn(v0));
        float h1 = __bfloat162float(__float2bfloat16_rn(v1));
        hi[i] = pack_bf16(v0, v1);
        lo[i] = pack_bf16(v0 - h0, v1 - h1);
    }
}

// ---------------- CSR build --------------------------------------------------
__global__ void zero_csr_k(int* deg, int* cursor) {
    int i = blockIdx.x * blockDim.x + threadIdx.x;
    if (i < NNODES) { deg[i] = 0; cursor[i] = 0; }
}
__global__ void hist_k(const int* __restrict__ dst, int* __restrict__ deg) {
    int e = blockIdx.x * blockDim.x + threadIdx.x;
    if (e < NEDGES) atomicAdd(&deg[dst[e]], 1);
}
__global__ void scan_k(const int* __restrict__ deg, int* __restrict__ rowptr) {
    __shared__ int sh[1024];
    __shared__ int s_carry;
    int tid = threadIdx.x;
    if (tid == 0) s_carry = 0;
    __syncthreads();
    for (int base = 0; base < NNODES; base += 1024) {
        int v = (base + tid < NNODES) ? deg[base + tid] : 0;
        sh[tid] = v;
        __syncthreads();
        for (int off = 1; off < 1024; off <<= 1) {
            int add = (tid >= off) ? sh[tid - off] : 0;
            __syncthreads();
            sh[tid] += add;
            __syncthreads();
        }
        if (base + tid < NNODES) rowptr[base + tid] = s_carry + sh[tid] - v;
        __syncthreads();
        if (tid == 1023) s_carry += sh[1023];
        __syncthreads();
    }
    if (tid == 0) rowptr[NNODES] = s_carry;
}
__global__ void fill_k(const int* __restrict__ src, const int* __restrict__ dst,
                       const int* __restrict__ rowptr, int* __restrict__ cursor,
                       int* __restrict__ colidx) {
    int e = blockIdx.x * blockDim.x + threadIdx.x;
    if (e < NEDGES) {
        int d = dst[e];
        int pos = atomicAdd(&cursor[d], 1);
        colidx[rowptr[d] + pos] = src[e];
    }
}

// z[n] = (1+eps)*h[n] + sum_{s in in(n)} h[s]
__global__ void gather_agg_k(const float* __restrict__ h, float* __restrict__ z,
                             const int* __restrict__ rowptr, const int* __restrict__ colidx,
                             const float* __restrict__ eps, int d) {
    int n = blockIdx.x;
    int tid = threadIdx.x;     // 128
    int e0 = rowptr[n], e1 = rowptr[n + 1];
    float coef = 1.0f + __ldg(eps);
    const float* hr = h + (size_t)n * d;
    float acc[4];
#pragma unroll
    for (int j = 0; j < 4; j++) {
        int i = tid + 128 * j;
        acc[j] = (i < d) ? coef * hr[i] : 0.0f;
    }
    for (int e = e0; e < e1; e++) {
        const float* hs = h + (size_t)colidx[e] * d;
#pragma unroll
        for (int j = 0; j < 4; j++) {
            int i = tid + 128 * j;
            if (i < d) acc[j] += hs[i];
        }
    }
    float* zr = z + (size_t)n * d;
#pragma unroll
    for (int j = 0; j < 4; j++) {
        int i = tid + 128 * j;
        if (i < d) zr[i] = acc[j];
    }
}

// ---------------- shared epilogue --------------------------------------------
// acc tile owner: rows r0=mb+g, r1=mb+g+8; cols nb, nb+1 (adjacent n, nb even)
template <int ACT, int OUT_SPLIT>
__device__ __forceinline__ void epi_store(
    float* acc2 /*[4]*/, int r0, int r1, int nb, int M,
    float s0, float s1, float b0, float b1,
    float* __restrict__ Cf, uint32_t* __restrict__ Oh, uint32_t* __restrict__ Ol) {
    float v0 = acc2[0] * s0 + b0, v1 = acc2[1] * s1 + b1;
    float w0 = acc2[2] * s0 + b0, w1 = acc2[3] * s1 + b1;
    if (ACT == 0) {
        v0 = fmaxf(v0, 0.f); v1 = fmaxf(v1, 0.f);
        w0 = fmaxf(w0, 0.f); w1 = fmaxf(w1, 0.f);
    } else {
        v0 = tanhf(v0); v1 = tanhf(v1);
        w0 = tanhf(w0); w1 = tanhf(w1);
    }
    if (OUT_SPLIT) {
        int wc = nb >> 1;
        if (r0 < M) {
            float h0 = __bfloat162float(__float2bfloat16_rn(v0));
            float h1 = __bfloat162float(__float2bfloat16_rn(v1));
            Oh[(size_t)r0 * PWORDS + wc] = pack_bf16(v0, v1);
            Ol[(size_t)r0 * PWORDS + wc] = pack_bf16(v0 - h0, v1 - h1);
        }
        if (r1 < M) {
            float h0 = __bfloat162float(__float2bfloat16_rn(w0));
            float h1 = __bfloat162float(__float2bfloat16_rn(w1));
            Oh[(size_t)r1 * PWORDS + wc] = pack_bf16(w0, w1);
            Ol[(size_t)r1 * PWORDS + wc] = pack_bf16(w0 - h0, w1 - h1);
        }
    } else {
        if (r0 < M) *(float2*)(Cf + (size_t)r0 * DIM + nb) = make_float2(v0, v1);
        if (r1 < M) *(float2*)(Cf + (size_t)r1 * DIM + nb) = make_float2(w0, w1);
    }
}

// ---------------- GEMM A-path 1: fp32 input, on-the-fly split (R12-validated)-
#define A_STR 20
#define B_STR 88

template <int ACT, int OUT_SPLIT>
__launch_bounds__(256)
__global__ void gemm_bf_k(const float* __restrict__ A,
                          const uint32_t* __restrict__ Whi,
                          const uint32_t* __restrict__ Wlo,
                          float* __restrict__ Cf,
                          uint32_t* __restrict__ Oh, uint32_t* __restrict__ Ol,
                          int M, int K, int Kpad,
                          const float* __restrict__ colscale,
                          const float* __restrict__ colbias) {
    __shared__ uint32_t Ahi[128 * A_STR], Alo[128 * A_STR];
    __shared__ uint32_t Bhi[16 * B_STR],  Blo[16 * B_STR];

    int tid  = threadIdx.x;
    int lane = tid & 31, wid = tid >> 5;
    int warpM = wid & 3, warpN = wid >> 2;
    int g = lane >> 2, t = lane & 3;
    int m0 = blockIdx.y * 128;
    int n0 = blockIdx.x * 80;

    float acc[2][5][4];
#pragma unroll
    for (int mt = 0; mt < 2; mt++)
#pragma unroll
        for (int nt = 0; nt < 5; nt++)
#pragma unroll
            for (int i = 0; i < 4; i++) acc[mt][nt][i] = 0.0f;

    bool vec4 = ((K & 3) == 0);
    int ntk = Kpad >> 5;

    for (int tk = 0; tk < ntk; tk++) {
        int k0 = tk << 5;
#pragma unroll
        for (int i = 0; i < 4; i++) {
            int slot = tid + (i << 8);
            int r = slot >> 3, c4 = (slot & 7) << 2;
            int gm = m0 + r, gk = k0 + c4;
            float4 v = make_float4(0.f, 0.f, 0.f, 0.f);
            if (gm < M) {
                if (vec4 && gk + 3 < K) {
                    v = *(const float4*)(A + (size_t)gm * K + gk);
                } else {
                    if (gk + 0 < K) v.x = A[(size_t)gm * K + gk + 0];
                    if (gk + 1 < K) v.y = A[(size_t)gm * K + gk + 1];
                    if (gk + 2 < K) v.z = A[(size_t)gm * K + gk + 2];
                    if (gk + 3 < K) v.w = A[(size_t)gm * K + gk + 3];
                }
            }
            float hx = __bfloat162float(__float2bfloat16_rn(v.x));
            float hy = __bfloat162float(__float2bfloat16_rn(v.y));
            float hz = __bfloat162float(__float2bfloat16_rn(v.z));
            float hw = __bfloat162float(__float2bfloat16_rn(v.w));
            int widx = r * A_STR + (c4 >> 1);
            *(uint2*)&Ahi[widx] = make_uint2(pack_bf16(v.x, v.y), pack_bf16(v.z, v.w));
            *(uint2*)&Alo[widx] = make_uint2(pack_bf16(v.x - hx, v.y - hy),
                                             pack_bf16(v.z - hz, v.w - hw));
        }
        {
            int kp0 = tk << 4;
#pragma unroll
            for (int i = 0; i < 2; i++) {
                int slot = tid + (i << 8);
                if (slot < 320) {
                    int r = slot / 20, q = slot % 20;
                    size_t gg = (size_t)(kp0 + r) * 400 + n0 + (q << 2);
                    int widx = r * B_STR + (q << 2);
                    *(uint4*)&Bhi[widx] = *(const uint4*)(Whi + gg);
                    *(uint4*)&Blo[widx] = *(const uint4*)(Wlo + gg);
                }
            }
        }
        __syncthreads();

#pragma unroll
        for (int s = 0; s < 2; s++) {
            int kp = (s << 3) + t;
            uint32_t ah[2][4], al[2][4];
#pragma unroll
            for (int mt = 0; mt < 2; mt++) {
                int base = (warpM * 32 + mt * 16 + g) * A_STR + kp;
                ah[mt][0] = Ahi[base];
                ah[mt][1] = Ahi[base + 8 * A_STR];
                ah[mt][2] = Ahi[base + 4];
                ah[mt][3] = Ahi[base + 8 * A_STR + 4];
                al[mt][0] = Alo[base];
                al[mt][1] = Alo[base + 8 * A_STR];
                al[mt][2] = Alo[base + 4];
                al[mt][3] = Alo[base + 8 * A_STR + 4];
            }
            uint32_t bh[5][2], bl[5][2];
#pragma unroll
            for (int nt = 0; nt < 5; nt++) {
                int idx = kp * B_STR + warpN * 40 + nt * 8 + g;
                bh[nt][0] = Bhi[idx];
                bh[nt][1] = Bhi[idx + 4 * B_STR];
                bl[nt][0] = Blo[idx];
                bl[nt][1] = Blo[idx + 4 * B_STR];
            }
#pragma unroll
            for (int mt = 0; mt < 2; mt++)
#pragma unroll
                for (int nt = 0; nt < 5; nt++) {
                    mma16(acc[mt][nt], al[mt], bh[nt]);
                    mma16(acc[mt][nt], ah[mt], bl[nt]);
                    mma16(acc[mt][nt], ah[mt], bh[nt]);
                }
        }
        __syncthreads();
    }

#pragma unroll
    for (int mt = 0; mt < 2; mt++) {
        int mb = m0 + warpM * 32 + mt * 16;
#pragma unroll
        for (int nt = 0; nt < 5; nt++) {
            int nb = n0 + warpN * 40 + nt * 8 + 2 * t;
            float s0 = colscale ? __ldg(&colscale[nb])     : 1.0f;
            float s1 = colscale ? __ldg(&colscale[nb + 1]) : 1.0f;
            float b0 = __ldg(&colbias[nb]);
            float b1 = __ldg(&colbias[nb + 1]);
            epi_store<ACT, OUT_SPLIT>(acc[mt][nt], mb + g, mb + g + 8, nb, M,
                                      s0, s1, b0, b1, Cf, Oh, Ol);
        }
    }
}

// ---------------- GEMM A-path 2: pre-split input, cp.async 2-stage pipeline --
// byte offsets within a stage
#define OFS_ALO 10240
#define OFS_BHI 20480
#define OFS_BLO 26112
#define STG_B   31744
#define STG_W   (STG_B / 4)

template <int ACT, int OUT_SPLIT>
__launch_bounds__(256)
__global__ void gemm_sp_k(const uint32_t* __restrict__ Ah, const uint32_t* __restrict__ Al,
                          const uint32_t* __restrict__ Wh, const uint32_t* __restrict__ Wl,
                          float* __restrict__ Cf,
                          uint32_t* __restrict__ Oh, uint32_t* __restrict__ Ol,
                          int M, const float* __restrict__ colbias) {
    extern __shared__ uint32_t smw[];
    uint32_t sb = smem_u32(smw);

    int tid  = threadIdx.x;
    int lane = tid & 31, wid = tid >> 5;
    int warpM = wid & 3, warpN = wid >> 2;
    int g = lane >> 2, t = lane & 3;
    int m0 = blockIdx.y * 128;
    int n0 = blockIdx.x * 80;

    float acc[2][5][4];
#pragma unroll
    for (int mt = 0; mt < 2; mt++)
#pragma unroll
        for (int nt = 0; nt < 5; nt++)
#pragma unroll
            for (int i = 0; i < 4; i++) acc[mt][nt][i] = 0.0f;

    const int ntk = 13;   // K=400 -> 208 pair-words = 13 tiles of 16

    // stage loader: A 1024 chunks (2 planes x 128 rows x 4), B 640 (2 x 16 x 20)
    auto load_st = [&](int tk) {
        uint32_t base = sb + (tk & 1) * STG_B;
        int k0w = tk << 4;
#pragma unroll
        for (int i = 0; i < 4; i++) {
            int slot = tid + (i << 8);
            int plane = slot >> 9;
            int rr = (slot & 511) >> 2, q = slot & 3;
            int gm = m0 + rr;
            if (gm >= M) gm = M - 1;                       // clamp (finite garbage)
            const uint32_t* sp = (plane ? Al : Ah) + (size_t)gm * PWORDS + k0w + (q << 2);
            uint32_t da = base + (plane ? OFS_ALO : 0) + rr * 80 + (q << 4);
            CP16(da, sp);
        }
#pragma unroll
        for (int i = 0; i < 3; i++) {
            int slot = tid + (i << 8);
            if (slot < 640) {
                int plane = (slot >= 320) ? 1 : 0;
                int s2 = slot - plane * 320;
                int rr = s2 / 20, q = s2 - rr * 20;
                const uint32_t* sp = (plane ? Wl : Wh) + (size_t)(k0w + rr) * 400 + n0 + (q << 2);
                uint32_t da = base + (plane ? OFS_BLO : OFS_BHI) + rr * 352 + (q << 4);
                CP16(da, sp);
            }
        }
        CP_COMMIT();
    };

    load_st(0);
    for (int tk = 0; tk < ntk; tk++) {
        if (tk + 1 < ntk) load_st(tk + 1);
        else CP_COMMIT();                 // empty group keeps wait count aligned
        CP_WAIT1();
        __syncthreads();

        const uint32_t* Ahi = smw + (tk & 1) * STG_W;
        const uint32_t* Alo = Ahi + OFS_ALO / 4;
        const uint32_t* Bhi = Ahi + OFS_BHI / 4;
        const uint32_t* Blo = Ahi + OFS_BLO / 4;

#pragma unroll
        for (int s = 0; s < 2; s++) {
            int kp = (s << 3) + t;
            uint32_t ah[2][4], al[2][4];
#pragma unroll
            for (int mt = 0; mt < 2; mt++) {
                int base = (warpM * 32 + mt * 16 + g) * A_STR + kp;
                ah[mt][0] = Ahi[base];
                ah[mt][1] = Ahi[base + 8 * A_STR];
                ah[mt][2] = Ahi[base + 4];
                ah[mt][3] = Ahi[base + 8 * A_STR + 4];
                al[mt][0] = Alo[base];
                al[mt][1] = Alo[base + 8 * A_STR];
                al[mt][2] = Alo[base + 4];
                al[mt][3] = Alo[base + 8 * A_STR + 4];
            }
            uint32_t bh[5][2], bl[5][2];
#pragma unroll
            for (int nt = 0; nt < 5; nt++) {
                int idx = kp * B_STR + warpN * 40 + nt * 8 + g;
                bh[nt][0] = Bhi[idx];
                bh[nt][1] = Bhi[idx + 4 * B_STR];
                bl[nt][0] = Blo[idx];
                bl[nt][1] = Blo[idx + 4 * B_STR];
            }
#pragma unroll
            for (int mt = 0; mt < 2; mt++)
#pragma unroll
                for (int nt = 0; nt < 5; nt++) {
                    mma16(acc[mt][nt], al[mt], bh[nt]);
                    mma16(acc[mt][nt], ah[mt], bl[nt]);
                    mma16(acc[mt][nt], ah[mt], bh[nt]);
                }
        }
        __syncthreads();
    }

#pragma unroll
    for (int mt = 0; mt < 2; mt++) {
        int mb = m0 + warpM * 32 + mt * 16;
#pragma unroll
        for (int nt = 0; nt < 5; nt++) {
            int nb = n0 + warpN * 40 + nt * 8 + 2 * t;
            float b0 = __ldg(&colbias[nb]);
            float b1 = __ldg(&colbias[nb + 1]);
            epi_store<ACT, OUT_SPLIT>(acc[mt][nt], mb + g, mb + g + 8, nb, M,
                                      1.0f, 1.0f, b0, b1, Cf, Oh, Ol);
        }
    }
}

// ---------------- pooling ----------------------------------------------------
__global__ void pool_init_k() {
    for (int i = blockIdx.x * blockDim.x + threadIdx.x; i < NGRAPH * DIM;
         i += gridDim.x * blockDim.x) {
        g_mx[i] = -FLT_MAX;
        g_sm[i] = 0.0f;
        if (i < NGRAPH) g_cnt[i] = 0.0f;
    }
}
__device__ __forceinline__ void atomicMaxF(float* addr, float v) {
    if (v >= 0.0f) atomicMax((int*)addr, __float_as_int(v));
    else           atomicMin((unsigned int*)addr, __float_as_uint(v));
}
__global__ void pool_acc_k(const float* __restrict__ h, const int* __restrict__ batch) {
    for (int i = blockIdx.x * blockDim.x + threadIdx.x; i < NNODES * DIM;
         i += gridDim.x * blockDim.x) {
        int n = i / DIM, d = i - n * DIM;
        int g = batch[n];
        float v = h[i];
        atomicAdd(&g_sm[g * DIM + d], v);
        atomicMaxF(&g_mx[g * DIM + d], v);
    }
}
__global__ void count_k(const int* __restrict__ batch) {
    for (int n = blockIdx.x * blockDim.x + threadIdx.x; n < NNODES;
         n += gridDim.x * blockDim.x)
        atomicAdd(&g_cnt[batch[n]], 1.0f);
}
__global__ void final_k(const float* __restrict__ ow, const float* __restrict__ ob,
                        float* __restrict__ out) {
    int g = blockIdx.x;
    __shared__ float red[256];
    float c = fmaxf(g_cnt[g], 1.0f);
    float acc = 0.0f;
    for (int d = threadIdx.x; d < DIM; d += 256) {
        acc += g_mx[g * DIM + d] * ow[d];
        acc += (g_sm[g * DIM + d] / c) * ow[DIM + d];
    }
    red[threadIdx.x] = acc;
    __syncthreads();
    for (int s = 128; s > 0; s >>= 1) {
        if (threadIdx.x < s) red[threadIdx.x] += red[threadIdx.x + s];
        __syncthreads();
    }
    if (threadIdx.x == 0) out[g] = red[0] + ob[0];
}

// ---------------- orchestration ----------------------------------------------
extern "C" void kernel_launch(void* const* d_in, const int* in_sizes, int n_in,
                              void* d_out, int out_size) {
    const float* x     = (const float*)d_in[0];
    const int*   eidx  = (const int*)d_in[1];
    const int*   batch = (const int*)d_in[2];
    int o = (in_sizes[3] == 1) ? 4 : 3;

    const float* m1w1  = (const float*)d_in[o + 0];
    const float* m1b1  = (const float*)d_in[o + 1];
    const float* m1g   = (const float*)d_in[o + 2];
    const float* m1bb  = (const float*)d_in[o + 3];
    const float* m1m   = (const float*)d_in[o + 4];
    const float* m1v   = (const float*)d_in[o + 5];
    const float* m1w2  = (const float*)d_in[o + 6];
    const float* m1b2  = (const float*)d_in[o + 7];
    const float* m2w1  = (const float*)d_in[o + 8];
    const float* m2b1  = (const float*)d_in[o + 9];
    const float* m2g   = (const float*)d_in[o + 10];
    const float* m2bb  = (const float*)d_in[o + 11];
    const float* m2m   = (const float*)d_in[o + 12];
    const float* m2v   = (const float*)d_in[o + 13];
    const float* m2w2  = (const float*)d_in[o + 14];
    const float* m2b2  = (const float*)d_in[o + 15];
    const float* o1w   = (const float*)d_in[o + 16];
    const float* o1b   = (const float*)d_in[o + 17];
    const float* o2w   = (const float*)d_in[o + 18];
    const float* o2b   = (const float*)d_in[o + 19];
    const float* o3w   = (const float*)d_in[o + 20];
    const float* o3b   = (const float*)d_in[o + 21];
    const float* ow    = (const float*)d_in[o + 22];
    const float* ob    = (const float*)d_in[o + 23];
    const float* eps1  = (const float*)d_in[o + 24];
    const float* eps2  = (const float*)d_in[o + 25];
    const float* eps3  = (const float*)d_in[o + 26];

    const int* src = eidx;
    const int* dst = eidx + NEDGES;

    float *bufA, *bufB, *s1, *fb1, *s2, *fb2;
    int *deg, *cursor, *rowptr, *colidx;
    uint32_t *wph, *wpl, *p1h, *p1l, *p2h, *p2l;
    cudaGetSymbolAddress((void**)&bufA, g_bufA);
    cudaGetSymbolAddress((void**)&bufB, g_bufB);
    cudaGetSymbolAddress((void**)&s1,  g_s1);
    cudaGetSymbolAddress((void**)&fb1, g_fb1);
    cudaGetSymbolAddress((void**)&s2,  g_s2);
    cudaGetSymbolAddress((void**)&fb2, g_fb2);
    cudaGetSymbolAddress((void**)&deg,    g_deg);
    cudaGetSymbolAddress((void**)&cursor, g_cursor);
    cudaGetSymbolAddress((void**)&rowptr, g_rowptr);
    cudaGetSymbolAddress((void**)&colidx, g_colidx);
    cudaGetSymbolAddress((void**)&wph, g_wph);
    cudaGetSymbolAddress((void**)&wpl, g_wpl);
    cudaGetSymbolAddress((void**)&p1h, g_p1h);
    cudaGetSymbolAddress((void**)&p1l, g_p1l);
    cudaGetSymbolAddress((void**)&p2h, g_p2h);
    cudaGetSymbolAddress((void**)&p2l, g_p2l);

    cudaFuncSetAttribute(gemm_sp_k<0, 1>, cudaFuncAttributeMaxDynamicSharedMemorySize, 2 * STG_B);
    cudaFuncSetAttribute(gemm_sp_k<1, 0>, cudaFuncAttributeMaxDynamicSharedMemorySize, 2 * STG_B);

    dim3 ggrid(DIM / 80, (NNODES + 127) / 128);   // (5, 391)

    // BN fold + weight split + CSR build
    fold_bn_k<<<2, 256>>>(m1g, m1bb, m1m, m1v, m1b1, s1, fb1);
    fold_bn_k<<<2, 256>>>(m2g, m2bb, m2m, m2v, m2b1, s2, fb2);
    wsplit_k<<<(WROWS1 * 400 + 255) / 256, 256>>>(m1w1, wph + OFF_W1,   wpl + OFF_W1,   FIN, WROWS1);
    wsplit_k<<<(WROWSB * 400 + 255) / 256, 256>>>(m1w2, wph + OFF_M1W2, wpl + OFF_M1W2, DIM, WROWSB);
    wsplit_k<<<(WROWSB * 400 + 255) / 256, 256>>>(m2w1, wph + OFF_M2W1, wpl + OFF_M2W1, DIM, WROWSB);
    wsplit_k<<<(WROWSB * 400 + 255) / 256, 256>>>(m2w2, wph + OFF_M2W2, wpl + OFF_M2W2, DIM, WROWSB);
    wsplit_k<<<(WROWSB * 400 + 255) / 256, 256>>>(o1w,  wph + OFF_O1W,  wpl + OFF_O1W,  DIM, WROWSB);
    wsplit_k<<<(WROWSB * 400 + 255) / 256, 256>>>(o2w,  wph + OFF_O2W,  wpl + OFF_O2W,  DIM, WROWSB);
    wsplit_k<<<(WROWSB * 400 + 255) / 256, 256>>>(o3w,  wph + OFF_O3W,  wpl + OFF_O3W,  DIM, WROWSB);
    zero_csr_k<<<(NNODES + 255) / 256, 256>>>(deg, cursor);
    hist_k<<<(NEDGES + 255) / 256, 256>>>(dst, deg);
    scan_k<<<1, 1024>>>(deg, rowptr);
    fill_k<<<(NEDGES + 255) / 256, 256>>>(src, dst, rowptr, cursor, colidx);

    // ---- GIN layer 1 ----
    gather_agg_k<<<NNODES, 128>>>(x, bufB, rowptr, colidx, eps1, FIN);
    gemm_bf_k<0, 1><<<ggrid, 256>>>(bufB, wph + OFF_W1, wpl + OFF_W1, nullptr, p1h, p1l,
                                    NNODES, FIN, KPAD1, s1, fb1);
    gemm_sp_k<0, 1><<<ggrid, 256, 2 * STG_B>>>(p1h, p1l, wph + OFF_M1W2, wpl + OFF_M1W2,
                                               nullptr, p2h, p2l, NNODES, m1b2);
    gemm_sp_k<1, 0><<<ggrid, 256, 2 * STG_B>>>(p2h, p2l, wph + OFF_O1W, wpl + OFF_O1W,
                                               bufA, nullptr, nullptr, NNODES, o1b);

    // ---- GIN layer 2 ----
    gather_agg_k<<<NNODES, 128>>>(bufA, bufB, rowptr, colidx, eps2, DIM);
    gemm_bf_k<0, 1><<<ggrid, 256>>>(bufB, wph + OFF_M2W1, wpl + OFF_M2W1, nullptr, p1h, p1l,
                                    NNODES, DIM, KPADB, s2, fb2);
    gemm_sp_k<0, 1><<<ggrid, 256, 2 * STG_B>>>(p1h, p1l, wph + OFF_M2W2, wpl + OFF_M2W2,
                                               nullptr, p2h, p2l, NNODES, m2b2);
    gemm_sp_k<1, 0><<<ggrid, 256, 2 * STG_B>>>(p2h, p2l, wph + OFF_O2W, wpl + OFF_O2W,
                                               bufA, nullptr, nullptr, NNODES, o2b);

    // ---- GIN layer 3 (mlp2 weights, eps3) ----
    gather_agg_k<<<NNODES, 128>>>(bufA, bufB, rowptr, colidx, eps3, DIM);
    gemm_bf_k<0, 1><<<ggrid, 256>>>(bufB, wph + OFF_M2W1, wpl + OFF_M2W1, nullptr, p1h, p1l,
                                    NNODES, DIM, KPADB, s2, fb2);
    gemm_sp_k<0, 1><<<ggrid, 256, 2 * STG_B>>>(p1h, p1l, wph + OFF_M2W2, wpl + OFF_M2W2,
                                               nullptr, p2h, p2l, NNODES, m2b2);
    gemm_sp_k<1, 0><<<ggrid, 256, 2 * STG_B>>>(p2h, p2l, wph + OFF_O3W, wpl + OFF_O3W,
                                               bufA, nullptr, nullptr, NNODES, o3b);

    // ---- pooling + head ----
    pool_init_k<<<128, 256>>>();
    count_k<<<(NNODES + 255) / 256, 256>>>(batch);
    pool_acc_k<<<4096, 256>>>(bufA, batch);
    final_k<<<NGRAPH, 256>>>(ow, ob, (float*)d_out);
}